// round 2
// baseline (speedup 1.0000x reference)
#include <cuda_runtime.h>

// VIN fully fused, f32x2-packed inner loop (sm_103a FFMA2):
//  r   = conv3x3(X, W_eff) + b_eff          (150-ch hidden layer collapsed)
//  qr  = conv3x3(r, q_w)   [10 maps, iteration-invariant]
//  v0  = max_l qr[l]
//  39x: v = max_l ( qr[l] + conv3x3(v, w[l]) )
// Channel pairs (2j,2j+1) ride the two f32x2 lanes; v stored duplicated in
// SMEM so LDS.64 yields the broadcast (p,p) operand directly.

#define THREADS   256
#define HH        64
#define WW        64
#define NPX       4096          // 64*64
#define LQ        10
#define LH        150
#define VW        72            // padded row stride (float2 units): 4 + 64 + 4
#define VH        66            // padded rows: 1 + 64 + 1
#define XPAD      4
// qr2: 5*NPX float2 ; vbuf2: VH*VW float2 ; rbuf: VH*VW float
#define SMEM_BYTES ((5 * NPX + VH * VW) * 8 + VH * VW * 4)

typedef unsigned long long u64;

__device__ __forceinline__ u64 fma2(u64 a, u64 b, u64 c) {
    u64 d;
    asm("fma.rn.f32x2 %0, %1, %2, %3;" : "=l"(d) : "l"(a), "l"(b), "l"(c));
    return d;
}
__device__ __forceinline__ u64 dup2(float v) {
    u64 d;
    asm("mov.b64 %0, {%1, %1};" : "=l"(d) : "f"(v));
    return d;
}
__device__ __forceinline__ void unpack2(u64 a, float& lo, float& hi) {
    asm("mov.b64 {%0, %1}, %2;" : "=f"(lo), "=f"(hi) : "l"(a));
}

__global__ void __launch_bounds__(THREADS, 1)
vin_kernel(const float* __restrict__ X, const float* __restrict__ h_w,
           const float* __restrict__ h_b, const float* __restrict__ r_w,
           const float* __restrict__ q_w, const float* __restrict__ ww,
           const int* __restrict__ kptr, float* __restrict__ out)
{
    extern __shared__ float smem[];
    float2* qr2   = (float2*)smem;            // [5][NPX], channel pairs
    float2* vbuf2 = qr2 + 5 * NPX;            // [VH][VW], (v,v) duplicated
    float*  rbuf  = (float*)(vbuf2 + VH * VW);// [VH][VW]
    __shared__ float  s_weff[19];             // W_eff(2x3x3) + b_eff
    __shared__ float  s_qw[LQ * 9];
    __shared__ float2 s_wp[45];               // packed loop weights (2j,2j+1)

    const int tid = threadIdx.x;
    const int b   = blockIdx.x;
    const float* Xb = X + (size_t)b * 2 * NPX;

    // ---- stage weights; collapse hidden layer ----
    if (tid < LQ * 9) s_qw[tid] = q_w[tid];
    if (tid < 45) {
        int j = tid / 9, t = tid % 9;
        s_wp[tid] = make_float2(ww[(2 * j) * 9 + t], ww[(2 * j + 1) * 9 + t]);
    }
    if (tid < 19) {
        float acc = 0.f;
        if (tid < 18) { for (int l = 0; l < LH; ++l) acc += r_w[l] * h_w[l * 18 + tid]; }
        else          { for (int l = 0; l < LH; ++l) acc += r_w[l] * h_b[l]; }
        s_weff[tid] = acc;
    }
    for (int i = tid; i < VH * VW; i += THREADS) {
        vbuf2[i] = make_float2(0.f, 0.f);
        rbuf[i]  = 0.f;
    }
    __syncthreads();

    // ---- r = conv3x3(X, W_eff) + b_eff ----
    for (int px = tid; px < NPX; px += THREADS) {
        int y = px >> 6, x = px & 63;
        float acc = s_weff[18];
        #pragma unroll
        for (int c = 0; c < 2; ++c)
            #pragma unroll
            for (int ky = 0; ky < 3; ++ky) {
                int iy = y - 1 + ky;
                if (iy < 0 || iy >= HH) continue;
                #pragma unroll
                for (int kx = 0; kx < 3; ++kx) {
                    int ix = x - 1 + kx;
                    if (ix < 0 || ix >= WW) continue;
                    acc += s_weff[c * 9 + ky * 3 + kx] * Xb[c * NPX + iy * WW + ix];
                }
            }
        rbuf[(y + 1) * VW + x + XPAD] = acc;
    }
    __syncthreads();

    // ---- qr pairs + v0 ----
    for (int px = tid; px < NPX; px += THREADS) {
        int y = px >> 6, x = px & 63;
        float n[9];
        #pragma unroll
        for (int ky = 0; ky < 3; ++ky)
            #pragma unroll
            for (int kx = 0; kx < 3; ++kx)
                n[ky * 3 + kx] = rbuf[(y + ky) * VW + (x + XPAD - 1 + kx)];
        float s[LQ];
        float vmax = -1e30f;
        #pragma unroll
        for (int l = 0; l < LQ; ++l) {
            float a = 0.f;
            #pragma unroll
            for (int t = 0; t < 9; ++t) a += s_qw[l * 9 + t] * n[t];
            s[l] = a;
            vmax = fmaxf(vmax, a);
        }
        #pragma unroll
        for (int j = 0; j < 5; ++j)
            qr2[j * NPX + px] = make_float2(s[2 * j], s[2 * j + 1]);
        vbuf2[(y + 1) * VW + x + XPAD] = make_float2(vmax, vmax);
    }
    __syncthreads();

    // ---- hoist 45 packed weights into registers ----
    u64 wp[45];
    #pragma unroll
    for (int i = 0; i < 45; ++i) {
        float2 f = s_wp[i];
        asm("mov.b64 %0, {%1, %2};" : "=l"(wp[i]) : "f"(f.x), "f"(f.y));
    }

    const int k = kptr[0];

    // ---- value iteration ----
    for (int it = 0; it < k - 1; ++it) {
        u64 resd[4][4];
        #pragma unroll
        for (int s = 0; s < 4; ++s) {
            int strip = s * THREADS + tid;       // 4-px horizontal strip
            int y  = strip >> 4;
            int x0 = (strip & 15) << 2;
            // neighborhood: 3 rows x 6 duplicated pairs (LDS.64 each)
            u64 np[3][6];
            #pragma unroll
            for (int r = 0; r < 3; ++r) {
                const u64* rowp = (const u64*)(vbuf2 + (y + r) * VW + x0 + 3);
                #pragma unroll
                for (int c = 0; c < 6; ++c) np[r][c] = rowp[c];
            }
            // accumulators init from qr pairs (2x LDS.128 per channel-pair)
            u64 acc[5][4];
            #pragma unroll
            for (int j = 0; j < 5; ++j) {
                const ulonglong2* qp =
                    (const ulonglong2*)(qr2 + j * NPX + (y << 6) + x0);
                ulonglong2 q0 = qp[0], q1 = qp[1];
                acc[j][0] = q0.x; acc[j][1] = q0.y;
                acc[j][2] = q1.x; acc[j][3] = q1.y;
            }
            // 5 pairs x 9 taps x 4 px packed FMAs
            #pragma unroll
            for (int j = 0; j < 5; ++j)
                #pragma unroll
                for (int ky = 0; ky < 3; ++ky)
                    #pragma unroll
                    for (int kx = 0; kx < 3; ++kx) {
                        u64 wv = wp[j * 9 + ky * 3 + kx];
                        #pragma unroll
                        for (int p = 0; p < 4; ++p)
                            acc[j][p] = fma2(np[ky][kx + p], wv, acc[j][p]);
                    }
            // max over 10 channels per pixel
            #pragma unroll
            for (int p = 0; p < 4; ++p) {
                float m = -1e30f;
                #pragma unroll
                for (int j = 0; j < 5; ++j) {
                    float lo, hi;
                    unpack2(acc[j][p], lo, hi);
                    m = fmaxf(m, fmaxf(lo, hi));
                }
                resd[s][p] = dup2(m);
            }
        }
        __syncthreads();   // all reads of old v done
        #pragma unroll
        for (int s = 0; s < 4; ++s) {
            int strip = s * THREADS + tid;
            int y  = strip >> 4;
            int x0 = (strip & 15) << 2;
            ulonglong2* dst = (ulonglong2*)(vbuf2 + (y + 1) * VW + XPAD + x0);
            dst[0] = make_ulonglong2(resd[s][0], resd[s][1]);
            dst[1] = make_ulonglong2(resd[s][2], resd[s][3]);
        }
        __syncthreads();   // new v visible
    }

    // ---- output [B,1,64,64] ----
    for (int px = tid; px < NPX; px += THREADS) {
        int y = px >> 6, x = px & 63;
        out[(size_t)b * NPX + px] = vbuf2[(y + 1) * VW + x + XPAD].x;
    }
}

extern "C" void kernel_launch(void* const* d_in, const int* in_sizes, int n_in,
                              void* d_out, int out_size) {
    const float* X   = (const float*)d_in[0];
    const float* h_w = (const float*)d_in[1];
    const float* h_b = (const float*)d_in[2];
    const float* r_w = (const float*)d_in[3];
    const float* q_w = (const float*)d_in[4];
    const float* w_  = (const float*)d_in[5];
    const int*   k   = (const int*)d_in[6];

    int B = in_sizes[0] / (2 * NPX);   // 128

    cudaFuncSetAttribute(vin_kernel,
                         cudaFuncAttributeMaxDynamicSharedMemorySize, SMEM_BYTES);
    vin_kernel<<<B, THREADS, SMEM_BYTES>>>(X, h_w, h_b, r_w, q_w, w_, k,
                                           (float*)d_out);
}

// round 3
// speedup vs baseline: 1.4080x; 1.4080x over previous
#include <cuda_runtime.h>

// VIN fully fused, channel-pair FFMA2, transposed conflict-free SMEM.
//  r   = conv3x3(X, W_eff) + b_eff      (150-ch hidden layer collapsed)
//  qr  = conv3x3(r, q_w)  [10 maps, iteration-invariant, stored as 5 ch-pairs
//                          column-major: qr2[j][x*65 + y]]
//  v0  = max_l qr[l]
//  39x: v = max_l ( qr[l] + conv3x3(v, w[l]) )
// v stored duplicated (v,v) column-major vdup[(x+1)*67 + (y+1)] so one LDS.64
// yields the broadcast operand for FFMA2 with channel-paired weights.
// Each thread owns one x-column and 16 y-rows (vertical sliding window).

#define THREADS 256
#define HH      64
#define WW      64
#define NPX     4096
#define LQ      10
#define LH      150
#define QS      65            // qr2 column stride (float2), odd -> conflict-free
#define S2      67            // vdup column stride (float2), odd -> conflict-free
#define RW      72            // rbuf row stride (float)
#define RH      66
// qr2: 5*64*QS f2 | vdup: 66*S2 f2 | rbuf: RH*RW f
#define QR2_F2   (5 * 64 * QS)
#define VDUP_F2  (66 * S2)
#define SMEM_BYTES (QR2_F2 * 8 + VDUP_F2 * 8 + RH * RW * 4)

typedef unsigned long long u64;

__device__ __forceinline__ u64 fma2(u64 a, u64 b, u64 c) {
    u64 d;
    asm("fma.rn.f32x2 %0, %1, %2, %3;" : "=l"(d) : "l"(a), "l"(b), "l"(c));
    return d;
}
__device__ __forceinline__ u64 dup2(float v) {
    u64 d;
    asm("mov.b64 %0, {%1, %1};" : "=l"(d) : "f"(v));
    return d;
}
__device__ __forceinline__ void unpack2(u64 a, float& lo, float& hi) {
    asm("mov.b64 {%0, %1}, %2;" : "=f"(lo), "=f"(hi) : "l"(a));
}

__global__ void __launch_bounds__(THREADS, 1)
vin_kernel(const float* __restrict__ X, const float* __restrict__ h_w,
           const float* __restrict__ h_b, const float* __restrict__ r_w,
           const float* __restrict__ q_w, const float* __restrict__ ww,
           const int* __restrict__ kptr, float* __restrict__ out)
{
    extern __shared__ float smem[];
    u64*   qr2  = (u64*)smem;                  // [5][64*QS] channel pairs, col-major
    u64*   vdup = qr2 + QR2_F2;                // [66][S2]   (v,v) pairs,   col-major
    float* rbuf = (float*)(vdup + VDUP_F2);    // [RH][RW]   plain r, row-major
    __shared__ float  s_weff[19];
    __shared__ float  s_qw[LQ * 9];
    __shared__ float2 s_wp[45];

    const int tid = threadIdx.x;
    const int b   = blockIdx.x;
    const float* Xb = X + (size_t)b * 2 * NPX;

    // ---- stage weights; collapse hidden layer ----
    if (tid < LQ * 9) s_qw[tid] = q_w[tid];
    if (tid < 45) {
        int j = tid / 9, t = tid % 9;
        s_wp[tid] = make_float2(ww[(2 * j) * 9 + t], ww[(2 * j + 1) * 9 + t]);
    }
    if (tid < 19) {
        float acc = 0.f;
        if (tid < 18) { for (int l = 0; l < LH; ++l) acc += r_w[l] * h_w[l * 18 + tid]; }
        else          { for (int l = 0; l < LH; ++l) acc += r_w[l] * h_b[l]; }
        s_weff[tid] = acc;
    }
    for (int i = tid; i < VDUP_F2; i += THREADS) vdup[i] = 0ull;
    for (int i = tid; i < RH * RW; i += THREADS) rbuf[i] = 0.f;
    __syncthreads();

    // ---- r = conv3x3(X, W_eff) + b_eff ----
    for (int px = tid; px < NPX; px += THREADS) {
        int y = px >> 6, x = px & 63;
        float acc = s_weff[18];
        #pragma unroll
        for (int c = 0; c < 2; ++c)
            #pragma unroll
            for (int ky = 0; ky < 3; ++ky) {
                int iy = y - 1 + ky;
                if (iy < 0 || iy >= HH) continue;
                #pragma unroll
                for (int kx = 0; kx < 3; ++kx) {
                    int ix = x - 1 + kx;
                    if (ix < 0 || ix >= WW) continue;
                    acc += s_weff[c * 9 + ky * 3 + kx] * Xb[c * NPX + iy * WW + ix];
                }
            }
        rbuf[(y + 1) * RW + x + 1] = acc;
    }
    __syncthreads();

    // ---- qr pairs (transposed) + v0 ----
    for (int px = tid; px < NPX; px += THREADS) {
        int y = px >> 6, x = px & 63;
        float n[9];
        #pragma unroll
        for (int ky = 0; ky < 3; ++ky)
            #pragma unroll
            for (int kx = 0; kx < 3; ++kx)
                n[ky * 3 + kx] = rbuf[(y + ky) * RW + x + kx];
        float s[LQ];
        float vmax = -1e30f;
        #pragma unroll
        for (int l = 0; l < LQ; ++l) {
            float a = 0.f;
            #pragma unroll
            for (int t = 0; t < 9; ++t) a += s_qw[l * 9 + t] * n[t];
            s[l] = a;
            vmax = fmaxf(vmax, a);
        }
        #pragma unroll
        for (int j = 0; j < 5; ++j) {
            u64 p;
            asm("mov.b64 %0, {%1, %2};" : "=l"(p) : "f"(s[2 * j]), "f"(s[2 * j + 1]));
            qr2[j * (64 * QS) + x * QS + y] = p;
        }
        vdup[(x + 1) * S2 + (y + 1)] = dup2(vmax);
    }
    __syncthreads();

    // ---- hoist 45 packed weights into registers ----
    u64 wp[45];
    #pragma unroll
    for (int i = 0; i < 45; ++i) {
        float2 f = s_wp[i];
        asm("mov.b64 %0, {%1, %2};" : "=l"(wp[i]) : "f"(f.x), "f"(f.y));
    }

    const int k  = kptr[0];
    const int x  = tid & 63;
    const int y0 = (tid >> 6) << 4;                 // 0,16,32,48
    const u64* vcol = vdup + x * S2;                // col (x-1) base; +c*S2 for dx
    const u64* qcol = qr2 + x * QS;
    u64*       wcol = vdup + (x + 1) * S2;          // write column

    // ---- value iteration: thread = column x, rows y0..y0+15 ----
    for (int it = 0; it < k - 1; ++it) {
        // window rows y0-1..y0+1  (vdup index y0..y0+2)
        u64 np[3][3];
        #pragma unroll
        for (int c = 0; c < 3; ++c) {
            const u64* col = vcol + c * S2;
            np[0][c] = col[y0];
            np[1][c] = col[y0 + 1];
            np[2][c] = col[y0 + 2];
        }
        float res[16];
        #pragma unroll
        for (int yy = 0; yy < 16; ++yy) {
            u64 acc[5];
            #pragma unroll
            for (int j = 0; j < 5; ++j) acc[j] = qcol[j * (64 * QS) + y0 + yy];
            #pragma unroll
            for (int j = 0; j < 5; ++j)
                #pragma unroll
                for (int ky = 0; ky < 3; ++ky)
                    #pragma unroll
                    for (int kx = 0; kx < 3; ++kx)
                        acc[j] = fma2(np[ky][kx], wp[j * 9 + ky * 3 + kx], acc[j]);
            float m0 = -1e30f, m1 = -1e30f;
            #pragma unroll
            for (int j = 0; j < 5; ++j) {
                float lo, hi;
                unpack2(acc[j], lo, hi);
                m0 = fmaxf(m0, lo);
                m1 = fmaxf(m1, hi);
            }
            res[yy] = fmaxf(m0, m1);
            if (yy < 15) {          // slide window down one row
                #pragma unroll
                for (int c = 0; c < 3; ++c) {
                    np[0][c] = np[1][c];
                    np[1][c] = np[2][c];
                    np[2][c] = vcol[c * S2 + y0 + yy + 3];
                }
            }
        }
        __syncthreads();            // all reads of old v done
        #pragma unroll
        for (int yy = 0; yy < 16; ++yy)
            wcol[y0 + yy + 1] = dup2(res[yy]);
        __syncthreads();            // new v visible
    }

    // ---- output [B,1,64,64] ----
    for (int px = tid; px < NPX; px += THREADS) {
        int y = px >> 6, xx = px & 63;
        float lo, hi;
        unpack2(vdup[(xx + 1) * S2 + (y + 1)], lo, hi);
        out[(size_t)b * NPX + px] = lo;
        (void)hi;
    }
}

extern "C" void kernel_launch(void* const* d_in, const int* in_sizes, int n_in,
                              void* d_out, int out_size) {
    const float* X   = (const float*)d_in[0];
    const float* h_w = (const float*)d_in[1];
    const float* h_b = (const float*)d_in[2];
    const float* r_w = (const float*)d_in[3];
    const float* q_w = (const float*)d_in[4];
    const float* w_  = (const float*)d_in[5];
    const int*   k   = (const int*)d_in[6];

    int B = in_sizes[0] / (2 * NPX);   // 128

    cudaFuncSetAttribute(vin_kernel,
                         cudaFuncAttributeMaxDynamicSharedMemorySize, SMEM_BYTES);
    vin_kernel<<<B, THREADS, SMEM_BYTES>>>(X, h_w, h_b, r_w, q_w, w_, k,
                                           (float*)d_out);
}

// round 6
// speedup vs baseline: 1.4116x; 1.0025x over previous
#include <cuda_runtime.h>

// VIN fully fused (rev b — symbol renamed, functionally identical to R4).
// Channel-pair FFMA2, transposed conflict-free SMEM, 384 threads
// (3 warps/SMSP), double-buffered v (1 barrier/iter).
//  r   = conv3x3(X, W_eff) + b_eff      (150-ch hidden layer collapsed)
//  qr  = conv3x3(r, q_w)   [5 channel-pairs, col-major qr2[j][x*65+y]]
//  v0  = max_l qr[l]
//  39x: v = max_l ( qr[l] + conv3x3(v, w[l]) )
// v stored plain col-major v[(x+1)*67 + (y+1)]; broadcast (v,v) pairs built
// with one mov.b64 per load. Thread = column x, 11-row band (6 bands).

#define THREADS 384
#define HH      64
#define WW      64
#define NPX     4096
#define LQ      10
#define LH      150
#define QS      65              // qr2 column stride (u64), odd
#define SV      67              // v column stride (float), odd
#define RW      72              // rbuf row stride (float)
#define RH      66
#define QR_F2   (5 * 64 * QS + 128)     // padded for garbage-row reads
#define V_F     (66 * SV + 96)          // padded
#define SMEM_BYTES (QR_F2 * 8 + 2 * V_F * 4 + RH * RW * 4)

typedef unsigned long long u64;

__device__ __forceinline__ u64 fma2(u64 a, u64 b, u64 c) {
    u64 d;
    asm("fma.rn.f32x2 %0, %1, %2, %3;" : "=l"(d) : "l"(a), "l"(b), "l"(c));
    return d;
}
__device__ __forceinline__ u64 dup2(float v) {
    u64 d;
    asm("mov.b64 %0, {%1, %1};" : "=l"(d) : "f"(v));
    return d;
}
__device__ __forceinline__ void unpack2(u64 a, float& lo, float& hi) {
    asm("mov.b64 {%0, %1}, %2;" : "=f"(lo), "=f"(hi) : "l"(a));
}

__global__ void __launch_bounds__(THREADS, 1)
vin_iter_kernel(const float* __restrict__ X, const float* __restrict__ h_w,
                const float* __restrict__ h_b, const float* __restrict__ r_w,
                const float* __restrict__ q_w, const float* __restrict__ ww,
                const int* __restrict__ kptr, float* __restrict__ out)
{
    extern __shared__ float smem[];
    u64*   qr2 = (u64*)smem;                   // [5][64*QS] ch-pairs, col-major
    float* vA  = (float*)(qr2 + QR_F2);        // [66*SV] plain v, col-major
    float* vB  = vA + V_F;
    float* rbuf = vB + V_F;                    // [RH][RW] row-major, prologue only
    __shared__ float  s_weff[19];
    __shared__ float  s_qw[LQ * 9];
    __shared__ float2 s_wp[45];

    const int tid = threadIdx.x;
    const int b   = blockIdx.x;
    const float* Xb = X + (size_t)b * 2 * NPX;

    // ---- stage weights; collapse hidden layer ----
    if (tid < LQ * 9) s_qw[tid] = q_w[tid];
    if (tid < 45) {
        int j = tid / 9, t = tid % 9;
        s_wp[tid] = make_float2(ww[(2 * j) * 9 + t], ww[(2 * j + 1) * 9 + t]);
    }
    if (tid < 19) {
        float acc = 0.f;
        if (tid < 18) { for (int l = 0; l < LH; ++l) acc += r_w[l] * h_w[l * 18 + tid]; }
        else          { for (int l = 0; l < LH; ++l) acc += r_w[l] * h_b[l]; }
        s_weff[tid] = acc;
    }
    for (int i = tid; i < V_F; i += THREADS) { vA[i] = 0.f; vB[i] = 0.f; }
    for (int i = tid; i < RH * RW; i += THREADS) rbuf[i] = 0.f;
    __syncthreads();

    // ---- r = conv3x3(X, W_eff) + b_eff ----
    for (int px = tid; px < NPX; px += THREADS) {
        int y = px >> 6, x = px & 63;
        float acc = s_weff[18];
        #pragma unroll
        for (int c = 0; c < 2; ++c)
            #pragma unroll
            for (int ky = 0; ky < 3; ++ky) {
                int iy = y - 1 + ky;
                if (iy < 0 || iy >= HH) continue;
                #pragma unroll
                for (int kx = 0; kx < 3; ++kx) {
                    int ix = x - 1 + kx;
                    if (ix < 0 || ix >= WW) continue;
                    acc += s_weff[c * 9 + ky * 3 + kx] * Xb[c * NPX + iy * WW + ix];
                }
            }
        rbuf[(y + 1) * RW + x + 1] = acc;
    }
    __syncthreads();

    // ---- qr pairs (col-major) + v0 into vA ----
    for (int px = tid; px < NPX; px += THREADS) {
        int y = px >> 6, x = px & 63;
        float n[9];
        #pragma unroll
        for (int ky = 0; ky < 3; ++ky)
            #pragma unroll
            for (int kx = 0; kx < 3; ++kx)
                n[ky * 3 + kx] = rbuf[(y + ky) * RW + x + kx];
        float s[LQ];
        float vmax = -1e30f;
        #pragma unroll
        for (int l = 0; l < LQ; ++l) {
            float a = 0.f;
            #pragma unroll
            for (int t = 0; t < 9; ++t) a += s_qw[l * 9 + t] * n[t];
            s[l] = a;
            vmax = fmaxf(vmax, a);
        }
        #pragma unroll
        for (int j = 0; j < 5; ++j) {
            u64 p;
            asm("mov.b64 %0, {%1, %2};" : "=l"(p) : "f"(s[2 * j]), "f"(s[2 * j + 1]));
            qr2[j * (64 * QS) + x * QS + y] = p;
        }
        vA[(x + 1) * SV + (y + 1)] = vmax;
    }
    __syncthreads();

    // ---- hoist 45 packed weights into registers ----
    u64 wp[45];
    #pragma unroll
    for (int i = 0; i < 45; ++i) {
        float2 f = s_wp[i];
        asm("mov.b64 %0, {%1, %2};" : "=l"(wp[i]) : "f"(f.x), "f"(f.y));
    }

    const int k  = kptr[0];
    const int x  = tid % 64;                 // column
    const int g  = tid / 64;                 // band 0..5
    const int y0 = g * 11;                   // band rows y0..y0+10 (writes y<64)
    const u64* qcol = qr2 + x * QS;

    float* cur = vA;
    float* alt = vB;

    // ---- value iteration (double-buffered, 1 barrier/iter) ----
    for (int it = 0; it < k - 1; ++it) {
        const float* c0 = cur + x * SV;          // v column x-1
        const float* c1 = c0 + SV;               // x
        const float* c2 = c1 + SV;               // x+1
        float* wcol = alt + (x + 1) * SV;

        // window rows (v rows y0-1..y0+1 -> indices y0..y0+2), duplicated pairs
        u64 np[3][3];
        #pragma unroll
        for (int r = 0; r < 3; ++r) {
            np[r][0] = dup2(c0[y0 + r]);
            np[r][1] = dup2(c1[y0 + r]);
            np[r][2] = dup2(c2[y0 + r]);
        }
        #pragma unroll
        for (int yy = 0; yy < 11; ++yy) {
            const int y = y0 + yy;
            u64 acc[5];
            #pragma unroll
            for (int j = 0; j < 5; ++j) acc[j] = qcol[j * (64 * QS) + y];
            #pragma unroll
            for (int j = 0; j < 5; ++j)
                #pragma unroll
                for (int ky = 0; ky < 3; ++ky)
                    #pragma unroll
                    for (int kx = 0; kx < 3; ++kx)
                        acc[j] = fma2(np[ky][kx], wp[j * 9 + ky * 3 + kx], acc[j]);
            float m0 = -1e30f, m1 = -1e30f;
            #pragma unroll
            for (int j = 0; j < 5; ++j) {
                float lo, hi;
                unpack2(acc[j], lo, hi);
                m0 = fmaxf(m0, lo);
                m1 = fmaxf(m1, hi);
            }
            if (y < 64) wcol[y + 1] = fmaxf(m0, m1);
            if (yy < 10) {                       // slide window down one row
                #pragma unroll
                for (int c = 0; c < 3; ++c) {
                    np[0][c] = np[1][c];
                    np[1][c] = np[2][c];
                }
                np[2][0] = dup2(c0[y0 + yy + 3]);
                np[2][1] = dup2(c1[y0 + yy + 3]);
                np[2][2] = dup2(c2[y0 + yy + 3]);
            }
        }
        __syncthreads();                         // alt fully written
        float* t = cur; cur = alt; alt = t;
    }

    // ---- output [B,1,64,64] from cur ----
    for (int px = tid; px < NPX; px += THREADS) {
        int y = px >> 6, xx = px & 63;
        out[(size_t)b * NPX + px] = cur[(xx + 1) * SV + (y + 1)];
    }
}

extern "C" void kernel_launch(void* const* d_in, const int* in_sizes, int n_in,
                              void* d_out, int out_size) {
    const float* X   = (const float*)d_in[0];
    const float* h_w = (const float*)d_in[1];
    const float* h_b = (const float*)d_in[2];
    const float* r_w = (const float*)d_in[3];
    const float* q_w = (const float*)d_in[4];
    const float* w_  = (const float*)d_in[5];
    const int*   k   = (const int*)d_in[6];

    int B = in_sizes[0] / (2 * NPX);   // 128

    cudaFuncSetAttribute(vin_iter_kernel,
                         cudaFuncAttributeMaxDynamicSharedMemorySize, SMEM_BYTES);
    vin_iter_kernel<<<B, THREADS, SMEM_BYTES>>>(X, h_w, h_b, r_w, q_w, w_, k,
                                                (float*)d_out);
}